// round 5
// baseline (speedup 1.0000x reference)
#include <cuda_runtime.h>
#include <math.h>
#include <stdint.h>

#define BB 1024
#define NN 512
#define EE 256
#define HH 128
#define AA 32
#define KC 32
#define APAD 136
#define WPAD 40

// ---------------- scratch (device globals) ----------------------------------
__device__ float g_d2    [(size_t)BB * HH];   // dec@W2 + b1 + b2
__device__ float g_d2wa  [(size_t)BB * AA];   // d2@Wa + ba
__device__ float g_c2base[(size_t)BB * HH];   // d2@Wwt + bwt
__device__ float g_wwt_hi[(size_t)EE * HH];   // tf32-hi of W1@Wwt  [e][h]
__device__ float g_wwt_lo[(size_t)EE * HH];   // tf32-lo
__device__ float g_wa_hi [(size_t)EE * AA];   // tf32-hi of W1@Wa   [e][a]
__device__ float g_wa_lo [(size_t)EE * AA];   // tf32-lo

__device__ __forceinline__ uint32_t f2tf32(float x) {
    uint32_t r;
    asm("cvt.rna.tf32.f32 %0, %1;" : "=r"(r) : "f"(x));
    return r;
}

#define MMA_TF32(C, A, B0, B1)                                                  \
    asm volatile(                                                               \
        "mma.sync.aligned.m16n8k8.row.col.f32.tf32.tf32.f32 "                   \
        "{%0,%1,%2,%3}, {%4,%5,%6,%7}, {%8,%9}, {%0,%1,%2,%3};"                 \
        : "+f"((C)[0]), "+f"((C)[1]), "+f"((C)[2]), "+f"((C)[3])                \
        : "r"((A)[0]), "r"((A)[1]), "r"((A)[2]), "r"((A)[3]),                   \
          "r"(B0), "r"(B1))

// ---------------- k_prew: W1@Wwt and W1@Wa, tf32 hi/lo split ----------------
__global__ void k_prew(const float* __restrict__ W1, const float* __restrict__ Wa,
                       const float* __restrict__ Wwt) {
    __shared__ float row[HH];
    int e = blockIdx.x, h = threadIdx.x;
    row[h] = W1[e * HH + h];
    __syncthreads();
    float acc = 0.f;
#pragma unroll 8
    for (int k = 0; k < HH; k++) acc = fmaf(row[k], Wwt[k * HH + h], acc);
    float hif = __uint_as_float(f2tf32(acc));
    g_wwt_hi[e * HH + h] = hif;
    g_wwt_lo[e * HH + h] = __uint_as_float(f2tf32(acc - hif));
    if (h < AA) {
        float a2 = 0.f;
#pragma unroll 8
        for (int k = 0; k < HH; k++) a2 = fmaf(row[k], Wa[k * AA + h], a2);
        float ahif = __uint_as_float(f2tf32(a2));
        g_wa_hi[e * AA + h] = ahif;
        g_wa_lo[e * AA + h] = __uint_as_float(f2tf32(a2 - ahif));
    }
}

// ---------------- k_d2v: d2, d2@Wa+ba, d2@Wwt+bwt ---------------------------
__global__ void k_d2v(const float* __restrict__ dec, const float* __restrict__ W2,
                      const float* __restrict__ b1, const float* __restrict__ b2,
                      const float* __restrict__ Wa, const float* __restrict__ ba,
                      const float* __restrict__ Wwt, const float* __restrict__ bwt) {
    __shared__ float ds[HH], d2s[HH];
    int b = blockIdx.x, h = threadIdx.x;
    ds[h] = dec[b * HH + h];
    __syncthreads();
    float acc = b1[h] + b2[h];
#pragma unroll 8
    for (int k = 0; k < HH; k++) acc = fmaf(ds[k], W2[k * HH + h], acc);
    d2s[h] = acc;
    g_d2[b * HH + h] = acc;
    __syncthreads();
    float c2 = bwt[h];
#pragma unroll 8
    for (int k = 0; k < HH; k++) c2 = fmaf(d2s[k], Wwt[k * HH + h], c2);
    g_c2base[b * HH + h] = c2;
    if (h < AA) {
        float aw = ba[h];
#pragma unroll 8
        for (int k = 0; k < HH; k++) aw = fmaf(d2s[k], Wa[k * AA + h], aw);
        g_d2wa[b * AA + h] = aw;
    }
}

// ---------------- k_fused: everything per batch in one CTA ------------------
__global__ void __launch_bounds__(256, 2)
k_fused(const float* __restrict__ enc, const float* __restrict__ W1,
        const float* __restrict__ Wct, const float* __restrict__ bct,
        const float* __restrict__ Va, const float* __restrict__ bva,
        const float* __restrict__ Vc, const float* __restrict__ bvc,
        const float* __restrict__ dem, const float* __restrict__ load,
        const void* __restrict__ veh_cap_raw, float* __restrict__ out) {
    extern __shared__ float sm[];
    float* AH  = sm;              // 4352
    float* AL  = AH + 4352;
    float* BH  = AL + 4352;
    float* BL  = BH + 4352;
    float* lg  = BL + 4352;       // 512 logits
    float* us  = lg + 512;        // 512 u / probs
    float* red = us + 512;        // 256
    float* ec  = red + 256;       // 256
    float* cts = ec + 256;        // 128
    float* c2s = cts + 128;       // 128
    float* vcs = c2s + 128;       // 128
    float* d2a = vcs + 128;       // 32
    float* vas = d2a + 32;        // 32
    float* ep  = vas + 32;        // 256
    float* sv  = ep + 256;        // 256 argmax vals
    int*   si  = (int*)(sv + 256);// 256 argmax idx
    __shared__ int   s_ptr;
    __shared__ float s_nd;

    const int tid  = threadIdx.x;
    const int lane = tid & 31, w = tid >> 5;
    const int gid  = lane >> 2, tig = lane & 3;
    const int b    = blockIdx.x;

    if (tid < AA) { d2a[tid] = g_d2wa[b * AA + tid]; vas[tid] = Va[tid]; }
    if (tid < HH) vcs[tid] = Vc[tid];
    const float bva0 = bva[0];

    const float* Ab = enc + (size_t)b * EE * NN;
    const int lk  = tid >> 3;          // k row 0..31
    const int lnq = (tid & 7) * 16;    // 16-col group

    // ================= stage U: u = tanh(enc^T@W1Wa + d2Wa)@Va + bva ========
    for (int nb = 0; nb < 4; nb++) {
        const int n0 = nb * 128;
        float c[4][4];
#pragma unroll
        for (int nt = 0; nt < 4; nt++)
#pragma unroll
            for (int q = 0; q < 4; q++) c[nt][q] = 0.f;

        for (int kt = 0; kt < 8; kt++) {
            __syncthreads();
            const float* arow = Ab + (size_t)(kt * KC + lk) * NN + n0 + lnq;
#pragma unroll
            for (int j = 0; j < 4; j++) {
                float4 v = *(const float4*)(arow + j * 4);
                float4 hi, lo;
                hi.x = __uint_as_float(f2tf32(v.x)); lo.x = __uint_as_float(f2tf32(v.x - hi.x));
                hi.y = __uint_as_float(f2tf32(v.y)); lo.y = __uint_as_float(f2tf32(v.y - hi.y));
                hi.z = __uint_as_float(f2tf32(v.z)); lo.z = __uint_as_float(f2tf32(v.z - hi.z));
                hi.w = __uint_as_float(f2tf32(v.w)); lo.w = __uint_as_float(f2tf32(v.w - hi.w));
                *(float4*)(AH + lk * APAD + lnq + j * 4) = hi;
                *(float4*)(AL + lk * APAD + lnq + j * 4) = lo;
            }
            {
                int col = (tid & 7) * 4;
                *(float4*)(BH + lk * WPAD + col) = *(const float4*)(g_wa_hi + (size_t)(kt * KC + lk) * AA + col);
                *(float4*)(BL + lk * WPAD + col) = *(const float4*)(g_wa_lo + (size_t)(kt * KC + lk) * AA + col);
            }
            __syncthreads();

            const int m = w * 16 + gid;
#pragma unroll
            for (int k8 = 0; k8 < 4; k8++) {
                const int kk = k8 * 8 + tig;
                uint32_t ah[4], al[4];
                ah[0] = __float_as_uint(AH[kk * APAD + m]);
                ah[1] = __float_as_uint(AH[kk * APAD + m + 8]);
                ah[2] = __float_as_uint(AH[(kk + 4) * APAD + m]);
                ah[3] = __float_as_uint(AH[(kk + 4) * APAD + m + 8]);
                al[0] = __float_as_uint(AL[kk * APAD + m]);
                al[1] = __float_as_uint(AL[kk * APAD + m + 8]);
                al[2] = __float_as_uint(AL[(kk + 4) * APAD + m]);
                al[3] = __float_as_uint(AL[(kk + 4) * APAD + m + 8]);
#pragma unroll
                for (int nt = 0; nt < 4; nt++) {
                    const int a = nt * 8 + gid;
                    uint32_t bh0 = __float_as_uint(BH[kk * WPAD + a]);
                    uint32_t bh1 = __float_as_uint(BH[(kk + 4) * WPAD + a]);
                    uint32_t bl0 = __float_as_uint(BL[kk * WPAD + a]);
                    uint32_t bl1 = __float_as_uint(BL[(kk + 4) * WPAD + a]);
                    MMA_TF32(c[nt], ah, bh0, bh1);
                    MMA_TF32(c[nt], al, bh0, bh1);
                    MMA_TF32(c[nt], ah, bl0, bl1);
                }
            }
        }
        // epilogue -> us
        float s0 = 0.f, s1 = 0.f;
#pragma unroll
        for (int nt = 0; nt < 4; nt++)
#pragma unroll
            for (int q = 0; q < 2; q++) {
                int a = nt * 8 + 2 * tig + q;
                s0 = fmaf(tanhf(c[nt][q]     + d2a[a]), vas[a], s0);
                s1 = fmaf(tanhf(c[nt][2 + q] + d2a[a]), vas[a], s1);
            }
        s0 += __shfl_xor_sync(0xffffffffu, s0, 1);
        s0 += __shfl_xor_sync(0xffffffffu, s0, 2);
        s1 += __shfl_xor_sync(0xffffffffu, s1, 1);
        s1 += __shfl_xor_sync(0xffffffffu, s1, 2);
        if (tig == 0) {
            us[n0 + w * 16 + gid]     = s0 + bva0;
            us[n0 + w * 16 + gid + 8] = s1 + bva0;
        }
    }
    __syncthreads();

    // ================= softmax over us ======================================
    {
        float u0 = us[tid], u1 = us[tid + 256];
        red[tid] = fmaxf(u0, u1);
        __syncthreads();
        for (int s = 128; s > 0; s >>= 1) {
            if (tid < s) red[tid] = fmaxf(red[tid], red[tid + s]);
            __syncthreads();
        }
        float mx = red[0];
        __syncthreads();
        float p0 = expf(u0 - mx), p1 = expf(u1 - mx);
        red[tid] = p0 + p1;
        __syncthreads();
        for (int s = 128; s > 0; s >>= 1) {
            if (tid < s) red[tid] += red[tid + s];
            __syncthreads();
        }
        float invZ = 1.f / red[0];
        us[tid] = p0 * invZ;
        us[tid + 256] = p1 * invZ;
    }
    __syncthreads();

    // ================= e_c = a^T enc ========================================
    for (int e = w; e < EE; e += 8) {
        const float* er = Ab + (size_t)e * NN;
        float s = 0.f;
#pragma unroll 4
        for (int n = lane; n < NN; n += 32) s = fmaf(us[n], er[n], s);
        s += __shfl_xor_sync(0xffffffffu, s, 16);
        s += __shfl_xor_sync(0xffffffffu, s, 8);
        s += __shfl_xor_sync(0xffffffffu, s, 4);
        s += __shfl_xor_sync(0xffffffffu, s, 2);
        s += __shfl_xor_sync(0xffffffffu, s, 1);
        if (lane == 0) ec[e] = s;
    }
    __syncthreads();

    // ================= c_t and c2 ==========================================
    if (tid < HH) {
        float acc = g_d2[b * HH + tid];
#pragma unroll 8
        for (int k = 0; k < EE; k++) acc = fmaf(ec[k], W1[k * HH + tid], acc);
        cts[tid] = acc;
    }
    __syncthreads();
    if (tid < HH) {
        float c2 = g_c2base[b * HH + tid] + bct[tid];
#pragma unroll 8
        for (int k = 0; k < HH; k++) c2 = fmaf(cts[k], Wct[k * HH + tid], c2);
        c2s[tid] = c2;
    }
    __syncthreads();

    // ================= logits = tanh(enc^T@W1Wwt + c2)@Vc + bvc =============
    const int m0 = (w >> 1) * 32;
    const int h0 = (w & 1) * 64;
    for (int nb = 0; nb < 4; nb++) {
        const int n0 = nb * 128;
        float c[2][8][4];
#pragma unroll
        for (int mt = 0; mt < 2; mt++)
#pragma unroll
            for (int nt = 0; nt < 8; nt++)
#pragma unroll
                for (int q = 0; q < 4; q++) c[mt][nt][q] = 0.f;

        for (int kt = 0; kt < 8; kt++) {
            __syncthreads();
            const float* arow = Ab + (size_t)(kt * KC + lk) * NN + n0 + lnq;
            const float* bhr  = g_wwt_hi + (size_t)(kt * KC + lk) * HH + lnq;
            const float* blr  = g_wwt_lo + (size_t)(kt * KC + lk) * HH + lnq;
#pragma unroll
            for (int j = 0; j < 4; j++) {
                float4 v = *(const float4*)(arow + j * 4);
                float4 hi, lo;
                hi.x = __uint_as_float(f2tf32(v.x)); lo.x = __uint_as_float(f2tf32(v.x - hi.x));
                hi.y = __uint_as_float(f2tf32(v.y)); lo.y = __uint_as_float(f2tf32(v.y - hi.y));
                hi.z = __uint_as_float(f2tf32(v.z)); lo.z = __uint_as_float(f2tf32(v.z - hi.z));
                hi.w = __uint_as_float(f2tf32(v.w)); lo.w = __uint_as_float(f2tf32(v.w - hi.w));
                *(float4*)(AH + lk * APAD + lnq + j * 4) = hi;
                *(float4*)(AL + lk * APAD + lnq + j * 4) = lo;
                *(float4*)(BH + lk * APAD + lnq + j * 4) = *(const float4*)(bhr + j * 4);
                *(float4*)(BL + lk * APAD + lnq + j * 4) = *(const float4*)(blr + j * 4);
            }
            __syncthreads();

#pragma unroll
            for (int k8 = 0; k8 < 4; k8++) {
                const int kk = k8 * 8 + tig;
                uint32_t ah[2][4], al[2][4];
#pragma unroll
                for (int mt = 0; mt < 2; mt++) {
                    const int m = m0 + mt * 16 + gid;
                    ah[mt][0] = __float_as_uint(AH[kk * APAD + m]);
                    ah[mt][1] = __float_as_uint(AH[kk * APAD + m + 8]);
                    ah[mt][2] = __float_as_uint(AH[(kk + 4) * APAD + m]);
                    ah[mt][3] = __float_as_uint(AH[(kk + 4) * APAD + m + 8]);
                    al[mt][0] = __float_as_uint(AL[kk * APAD + m]);
                    al[mt][1] = __float_as_uint(AL[kk * APAD + m + 8]);
                    al[mt][2] = __float_as_uint(AL[(kk + 4) * APAD + m]);
                    al[mt][3] = __float_as_uint(AL[(kk + 4) * APAD + m + 8]);
                }
#pragma unroll
                for (int nt = 0; nt < 8; nt++) {
                    const int h = h0 + nt * 8 + gid;
                    uint32_t bh0 = __float_as_uint(BH[kk * APAD + h]);
                    uint32_t bh1 = __float_as_uint(BH[(kk + 4) * APAD + h]);
                    uint32_t bl0 = __float_as_uint(BL[kk * APAD + h]);
                    uint32_t bl1 = __float_as_uint(BL[(kk + 4) * APAD + h]);
#pragma unroll
                    for (int mt = 0; mt < 2; mt++) {
                        MMA_TF32(c[mt][nt], ah[mt], bh0, bh1);
                        MMA_TF32(c[mt][nt], al[mt], bh0, bh1);
                        MMA_TF32(c[mt][nt], ah[mt], bl0, bl1);
                    }
                }
            }
        }
        // epilogue: tanh + dot Vc; lanewise reduce + cross-warp via ep
#pragma unroll
        for (int mt = 0; mt < 2; mt++) {
            float s0 = 0.f, s1 = 0.f;
#pragma unroll
            for (int nt = 0; nt < 8; nt++)
#pragma unroll
                for (int q = 0; q < 2; q++) {
                    int h = h0 + nt * 8 + 2 * tig + q;
                    s0 = fmaf(tanhf(c[mt][nt][q]     + c2s[h]), vcs[h], s0);
                    s1 = fmaf(tanhf(c[mt][nt][2 + q] + c2s[h]), vcs[h], s1);
                }
            s0 += __shfl_xor_sync(0xffffffffu, s0, 1);
            s0 += __shfl_xor_sync(0xffffffffu, s0, 2);
            s1 += __shfl_xor_sync(0xffffffffu, s1, 1);
            s1 += __shfl_xor_sync(0xffffffffu, s1, 2);
            if (tig == 0) {
                int r = m0 + mt * 16 + gid;
                ep[r * 2 + (w & 1)]       = s0;
                ep[(r + 8) * 2 + (w & 1)] = s1;
            }
        }
        __syncthreads();
        if (tid < 128)
            lg[n0 + tid] = ep[tid * 2] + ep[tid * 2 + 1] + bvc[0];
    }
    __syncthreads();

    // ================= final: log_softmax, mask, argmax, outputs ============
    {
        float l0 = lg[tid], l1 = lg[tid + 256];
        red[tid] = fmaxf(l0, l1);
        __syncthreads();
        for (int s = 128; s > 0; s >>= 1) {
            if (tid < s) red[tid] = fmaxf(red[tid], red[tid + s]);
            __syncthreads();
        }
        float mx = red[0];
        __syncthreads();
        red[tid] = expf(l0 - mx) + expf(l1 - mx);
        __syncthreads();
        for (int s = 128; s > 0; s >>= 1) {
            if (tid < s) red[tid] += red[tid + s];
            __syncthreads();
        }
        float lse = mx + logf(red[0]);

        float dm0 = dem[(size_t)b * NN + tid];
        float dm1 = dem[(size_t)b * NN + tid + 256];
        float ld  = load[b];
        const float NEGINF = __int_as_float(0xff800000);
        float lp0 = l0 - lse;
        float lp1 = l1 - lse;
        if (tid > 0 && (dm0 == 0.f || ld == 0.f)) lp0 = NEGINF;
        if (dm1 == 0.f || ld == 0.f)              lp1 = NEGINF;
        out[(size_t)b * NN + tid]       = lp0;
        out[(size_t)b * NN + tid + 256] = lp1;

        float v; int idx;
        if (lp1 > lp0) { v = lp1; idx = tid + 256; } else { v = lp0; idx = tid; }
        sv[tid] = v; si[tid] = idx;
        __syncthreads();
        for (int s = 128; s > 0; s >>= 1) {
            if (tid < s) {
                float v2 = sv[tid + s]; int i2 = si[tid + s];
                if (v2 > sv[tid] || (v2 == sv[tid] && i2 < si[tid])) { sv[tid] = v2; si[tid] = i2; }
            }
            __syncthreads();
        }
        if (tid == 0) {
            int ptr = si[0];
            float dsel = dem[(size_t)b * NN + ptr];
            float capf = *(const float*)veh_cap_raw;
            int   capi = *(const int*)veh_cap_raw;
            float cap = (capf > 0.5f && capf < 1.0e6f) ? capf : (float)capi;
            bool depot = (ptr == 0);
            float nload = depot ? cap : (ld - dsel);
            float ndsel = depot ? dsel : (dsel - nload);
            out[(size_t)BB * NN + b]      = (float)ptr;
            out[(size_t)BB * NN + BB + b] = nload;
            s_ptr = ptr; s_nd = ndsel;
        }
        __syncthreads();
        int ptr = s_ptr;
        float nd = s_nd;
        size_t base = (size_t)BB * NN + 2 * (size_t)BB + (size_t)b * NN;
        out[base + tid]       = (tid == ptr)       ? nd : dm0;
        out[base + tid + 256] = (tid + 256 == ptr) ? nd : dm1;
    }
}

// ---------------- launch ----------------------------------------------------
extern "C" void kernel_launch(void* const* d_in, const int* in_sizes, int n_in,
                              void* d_out, int out_size) {
    const float* dec  = (const float*)d_in[0];
    const float* enc  = (const float*)d_in[1];
    const float* load = (const float*)d_in[2];
    const float* dem  = (const float*)d_in[3];
    const float* W1   = (const float*)d_in[4];
    const float* b1   = (const float*)d_in[5];
    const float* W2   = (const float*)d_in[6];
    const float* b2   = (const float*)d_in[7];
    const float* Wwt  = (const float*)d_in[8];
    const float* bwt  = (const float*)d_in[9];
    const float* Wct  = (const float*)d_in[10];
    const float* bct  = (const float*)d_in[11];
    const float* Wa   = (const float*)d_in[12];
    const float* ba   = (const float*)d_in[13];
    const float* Va   = (const float*)d_in[14];
    const float* bva  = (const float*)d_in[15];
    const float* Vc   = (const float*)d_in[16];
    const float* bvc  = (const float*)d_in[17];
    const void*  vcap = (const void*)d_in[18];
    float* out = (float*)d_out;

    const int SMEM_F = (4 * 4352 + 512 + 512 + 256 + 256 + 128 + 128 + 128 +
                        32 + 32 + 256 + 256 + 256) * 4;   // 82688 B
    static int attr_done = 0;
    if (!attr_done) {
        cudaFuncSetAttribute(k_fused, cudaFuncAttributeMaxDynamicSharedMemorySize, SMEM_F);
        attr_done = 1;
    }

    k_prew<<<EE, HH>>>(W1, Wa, Wwt);
    k_d2v<<<BB, HH>>>(dec, W2, b1, b2, Wa, ba, Wwt, bwt);
    k_fused<<<BB, 256, SMEM_F>>>(enc, W1, Wct, bct, Va, bva, Vc, bvc,
                                 dem, load, vcap, out);
}

// round 6
// speedup vs baseline: 1.4275x; 1.4275x over previous
#include <cuda_runtime.h>
#include <math.h>
#include <stdint.h>

#define BB 1024
#define NN 512
#define EE 256
#define HH 128
#define AA 32
#define KC 32
#define APAD 136
#define WPAD 40

// ---------------- scratch (device globals) ----------------------------------
__device__ float g_u     [(size_t)BB * NN];   // u_t  [B,N]
__device__ float g_d2    [(size_t)BB * HH];   // dec@W2 + b1 + b2
__device__ float g_d2wa  [(size_t)BB * AA];   // d2@Wa + ba
__device__ float g_c2base[(size_t)BB * HH];   // d2@Wwt + bwt
__device__ float g_c2    [(size_t)BB * HH];   // c2base + c_t@Wct + bct
__device__ float g_wwt_hi[(size_t)EE * HH];   // tf32-hi of W1@Wwt  [e][h]
__device__ float g_wwt_lo[(size_t)EE * HH];   // tf32-lo
__device__ float g_wa_hi [(size_t)EE * AA];   // tf32-hi of W1@Wa   [e][a]
__device__ float g_wa_lo [(size_t)EE * AA];   // tf32-lo

__device__ __forceinline__ uint32_t f2tf32(float x) {
    uint32_t r;
    asm("cvt.rna.tf32.f32 %0, %1;" : "=r"(r) : "f"(x));
    return r;
}

#define MMA_TF32(C, A, B0, B1)                                                  \
    asm volatile(                                                               \
        "mma.sync.aligned.m16n8k8.row.col.f32.tf32.tf32.f32 "                   \
        "{%0,%1,%2,%3}, {%4,%5,%6,%7}, {%8,%9}, {%0,%1,%2,%3};"                 \
        : "+f"((C)[0]), "+f"((C)[1]), "+f"((C)[2]), "+f"((C)[3])                \
        : "r"((A)[0]), "r"((A)[1]), "r"((A)[2]), "r"((A)[3]),                   \
          "r"(B0), "r"(B1))

#define CP16(dst32, src) \
    asm volatile("cp.async.ca.shared.global [%0], [%1], 16;" :: "r"(dst32), "l"(src))
#define CP_COMMIT() asm volatile("cp.async.commit_group;")
#define CP_WAIT1()  asm volatile("cp.async.wait_group 1;")
#define CP_WAIT0()  asm volatile("cp.async.wait_group 0;")

// ---------------- k_pre: (prew for blockIdx < EE) + (d2v for the rest) ------
__global__ void k_pre(const float* __restrict__ W1, const float* __restrict__ Wa,
                      const float* __restrict__ Wwt, const float* __restrict__ dec,
                      const float* __restrict__ W2, const float* __restrict__ b1,
                      const float* __restrict__ b2, const float* __restrict__ ba,
                      const float* __restrict__ bwt) {
    __shared__ float row[HH], d2s[HH];
    int h = threadIdx.x;
    if (blockIdx.x < EE) {
        int e = blockIdx.x;
        row[h] = W1[e * HH + h];
        __syncthreads();
        float acc = 0.f;
#pragma unroll 8
        for (int k = 0; k < HH; k++) acc = fmaf(row[k], Wwt[k * HH + h], acc);
        float hif = __uint_as_float(f2tf32(acc));
        g_wwt_hi[e * HH + h] = hif;
        g_wwt_lo[e * HH + h] = __uint_as_float(f2tf32(acc - hif));
        if (h < AA) {
            float a2 = 0.f;
#pragma unroll 8
            for (int k = 0; k < HH; k++) a2 = fmaf(row[k], Wa[k * AA + h], a2);
            float ahif = __uint_as_float(f2tf32(a2));
            g_wa_hi[e * AA + h] = ahif;
            g_wa_lo[e * AA + h] = __uint_as_float(f2tf32(a2 - ahif));
        }
    } else {
        int b = blockIdx.x - EE;
        row[h] = dec[b * HH + h];
        __syncthreads();
        float acc = b1[h] + b2[h];
#pragma unroll 8
        for (int k = 0; k < HH; k++) acc = fmaf(row[k], W2[k * HH + h], acc);
        d2s[h] = acc;
        g_d2[b * HH + h] = acc;
        __syncthreads();
        float c2 = bwt[h];
#pragma unroll 8
        for (int k = 0; k < HH; k++) c2 = fmaf(d2s[k], Wwt[k * HH + h], c2);
        g_c2base[b * HH + h] = c2;
        if (h < AA) {
            float aw = ba[h];
#pragma unroll 8
            for (int k = 0; k < HH; k++) aw = fmaf(d2s[k], Wa[k * AA + h], aw);
            g_d2wa[b * AA + h] = aw;
        }
    }
}

// ---------------- k_u_mma: u = tanh(enc^T@W1Wa + d2Wa)@Va + bva -------------
// grid (4, B), block 256. Double-buffered cp.async pipeline.
__global__ void __launch_bounds__(256, 3)
k_u_mma(const float* __restrict__ enc, const float* __restrict__ Va,
        const float* __restrict__ bva) {
    extern __shared__ float sm[];
    float* AS  = sm;                      // 2 * KC*APAD
    float* BHs = AS + 2 * KC * APAD;      // 2 * KC*WPAD
    float* BLs = BHs + 2 * KC * WPAD;     // 2 * KC*WPAD
    float* d2a = BLs + 2 * KC * WPAD;     // 32
    float* vas = d2a + AA;                // 32

    const int tid  = threadIdx.x;
    const int lane = tid & 31, w = tid >> 5;
    const int gid  = lane >> 2, tig = lane & 3;
    const int b    = blockIdx.y;
    const int n0   = blockIdx.x * 128;

    if (tid < AA) { d2a[tid] = g_d2wa[b * AA + tid]; vas[tid] = Va[tid]; }
    const float bva0 = bva[0];

    const float* Ab = enc + (size_t)b * EE * NN + n0;
    const int lk   = tid >> 3;           // k row 0..31
    const int lnq  = (tid & 7) * 16;     // A col group
    const int colB = (tid & 7) * 4;      // B col group

    const uint32_t as_base = (uint32_t)__cvta_generic_to_shared(AS);
    const uint32_t bh_base = (uint32_t)__cvta_generic_to_shared(BHs);
    const uint32_t bl_base = (uint32_t)__cvta_generic_to_shared(BLs);

#define U_ISSUE(KT, BUF)                                                         \
    do {                                                                         \
        const float* arow_ = Ab + (size_t)((KT) * KC + lk) * NN + lnq;           \
        uint32_t ad_ = as_base + ((BUF) * KC * APAD + lk * APAD + lnq) * 4;      \
        CP16(ad_ + 0,  arow_ + 0);  CP16(ad_ + 16, arow_ + 4);                   \
        CP16(ad_ + 32, arow_ + 8);  CP16(ad_ + 48, arow_ + 12);                  \
        CP16(bh_base + ((BUF) * KC * WPAD + lk * WPAD + colB) * 4,               \
             g_wa_hi + (size_t)((KT) * KC + lk) * AA + colB);                    \
        CP16(bl_base + ((BUF) * KC * WPAD + lk * WPAD + colB) * 4,               \
             g_wa_lo + (size_t)((KT) * KC + lk) * AA + colB);                    \
    } while (0)

    float c[4][4];
#pragma unroll
    for (int nt = 0; nt < 4; nt++)
#pragma unroll
        for (int q = 0; q < 4; q++) c[nt][q] = 0.f;

    U_ISSUE(0, 0);
    CP_COMMIT();
    int cur = 0;
    for (int kt = 0; kt < 8; kt++) {
        if (kt < 7) { U_ISSUE(kt + 1, cur ^ 1); CP_COMMIT(); CP_WAIT1(); }
        else        { CP_WAIT0(); }
        __syncthreads();

        const float* Ac = AS + cur * KC * APAD;
        const float* Bh = BHs + cur * KC * WPAD;
        const float* Bl = BLs + cur * KC * WPAD;
        const int m = w * 16 + gid;
#pragma unroll
        for (int k8 = 0; k8 < 4; k8++) {
            const int kk = k8 * 8 + tig;
            float x0 = Ac[kk * APAD + m];
            float x1 = Ac[kk * APAD + m + 8];
            float x2 = Ac[(kk + 4) * APAD + m];
            float x3 = Ac[(kk + 4) * APAD + m + 8];
            uint32_t ah[4], al[4];
            ah[0] = f2tf32(x0); al[0] = f2tf32(x0 - __uint_as_float(ah[0]));
            ah[1] = f2tf32(x1); al[1] = f2tf32(x1 - __uint_as_float(ah[1]));
            ah[2] = f2tf32(x2); al[2] = f2tf32(x2 - __uint_as_float(ah[2]));
            ah[3] = f2tf32(x3); al[3] = f2tf32(x3 - __uint_as_float(ah[3]));
#pragma unroll
            for (int nt = 0; nt < 4; nt++) {
                const int a = nt * 8 + gid;
                uint32_t bh0 = __float_as_uint(Bh[kk * WPAD + a]);
                uint32_t bh1 = __float_as_uint(Bh[(kk + 4) * WPAD + a]);
                uint32_t bl0 = __float_as_uint(Bl[kk * WPAD + a]);
                uint32_t bl1 = __float_as_uint(Bl[(kk + 4) * WPAD + a]);
                MMA_TF32(c[nt], ah, bh0, bh1);
                MMA_TF32(c[nt], al, bh0, bh1);
                MMA_TF32(c[nt], ah, bl0, bl1);
            }
        }
        __syncthreads();
        cur ^= 1;
    }
#undef U_ISSUE

    // epilogue: tanh + dot Va, reduce over the 4 lanes sharing a row
    float s0 = 0.f, s1 = 0.f;
#pragma unroll
    for (int nt = 0; nt < 4; nt++)
#pragma unroll
        for (int q = 0; q < 2; q++) {
            int a = nt * 8 + 2 * tig + q;
            s0 = fmaf(tanhf(c[nt][q]     + d2a[a]), vas[a], s0);
            s1 = fmaf(tanhf(c[nt][2 + q] + d2a[a]), vas[a], s1);
        }
    s0 += __shfl_xor_sync(0xffffffffu, s0, 1);
    s0 += __shfl_xor_sync(0xffffffffu, s0, 2);
    s1 += __shfl_xor_sync(0xffffffffu, s1, 1);
    s1 += __shfl_xor_sync(0xffffffffu, s1, 2);
    if (tig == 0) {
        g_u[(size_t)b * NN + n0 + w * 16 + gid]     = s0 + bva0;
        g_u[(size_t)b * NN + n0 + w * 16 + gid + 8] = s1 + bva0;
    }
}

// ---------------- k_soft: softmax(u); e_c = a^T enc; c_t; c2 ----------------
__global__ void __launch_bounds__(256)
k_soft(const float* __restrict__ enc, const float* __restrict__ W1,
       const float* __restrict__ Wct, const float* __restrict__ bct) {
    __shared__ float us[NN];
    __shared__ float red[256];
    __shared__ float ec[EE];
    __shared__ float cts[HH];
    int b = blockIdx.x, tid = threadIdx.x;

    float u0 = g_u[(size_t)b * NN + tid];
    float u1 = g_u[(size_t)b * NN + 256 + tid];
    red[tid] = fmaxf(u0, u1);
    __syncthreads();
    for (int s = 128; s > 0; s >>= 1) {
        if (tid < s) red[tid] = fmaxf(red[tid], red[tid + s]);
        __syncthreads();
    }
    float mx = red[0];
    __syncthreads();
    float p0 = expf(u0 - mx), p1 = expf(u1 - mx);
    red[tid] = p0 + p1;
    __syncthreads();
    for (int s = 128; s > 0; s >>= 1) {
        if (tid < s) red[tid] += red[tid + s];
        __syncthreads();
    }
    float invZ = 1.f / red[0];
    us[tid] = p0 * invZ;
    us[tid + 256] = p1 * invZ;
    __syncthreads();

    // e_c[e] = sum_n a[n]*enc[b,e,n], float4-vectorized
    int w = tid >> 5, lane = tid & 31;
    const float* eb = enc + (size_t)b * EE * NN;
    const float4* us4 = (const float4*)us;
    for (int e = w; e < EE; e += 8) {
        const float4* er4 = (const float4*)(eb + (size_t)e * NN);
        float s = 0.f;
#pragma unroll 2
        for (int i = lane; i < NN / 4; i += 32) {
            float4 v = er4[i];
            float4 a = us4[i];
            s = fmaf(v.x, a.x, s); s = fmaf(v.y, a.y, s);
            s = fmaf(v.z, a.z, s); s = fmaf(v.w, a.w, s);
        }
        s += __shfl_xor_sync(0xffffffffu, s, 16);
        s += __shfl_xor_sync(0xffffffffu, s, 8);
        s += __shfl_xor_sync(0xffffffffu, s, 4);
        s += __shfl_xor_sync(0xffffffffu, s, 2);
        s += __shfl_xor_sync(0xffffffffu, s, 1);
        if (lane == 0) ec[e] = s;
    }
    __syncthreads();

    if (tid < HH) {
        float acc = g_d2[b * HH + tid];
#pragma unroll 8
        for (int k = 0; k < EE; k++) acc = fmaf(ec[k], W1[k * HH + tid], acc);
        cts[tid] = acc;
    }
    __syncthreads();
    if (tid < HH) {
        float c2 = g_c2base[b * HH + tid] + bct[tid];
#pragma unroll 8
        for (int k = 0; k < HH; k++) c2 = fmaf(cts[k], Wct[k * HH + tid], c2);
        g_c2[b * HH + tid] = c2;
    }
}

// ---------------- k_logits_mma: logits = tanh(enc^T@W1Wwt + c2)@Vc + bvc ----
// grid (4, B), block 256. Warp owns 16 n-rows x all 128 h. Double-buffered.
__global__ void __launch_bounds__(256, 2)
k_logits_mma(const float* __restrict__ enc, const float* __restrict__ Vc,
             const float* __restrict__ bvc, float* __restrict__ out) {
    extern __shared__ float sm[];
    float* AS  = sm;                      // 2 * KC*APAD
    float* BHs = AS + 2 * KC * APAD;      // 2 * KC*APAD
    float* BLs = BHs + 2 * KC * APAD;     // 2 * KC*APAD
    float* c2s = BLs + 2 * KC * APAD;     // 128
    float* vcs = c2s + HH;                // 128

    const int tid  = threadIdx.x;
    const int lane = tid & 31, w = tid >> 5;
    const int gid  = lane >> 2, tig = lane & 3;
    const int b    = blockIdx.y;
    const int n0   = blockIdx.x * 128;
    const int m0   = w * 16;

    if (tid < HH) { c2s[tid] = g_c2[b * HH + tid]; vcs[tid] = Vc[tid]; }
    const float bvc0 = bvc[0];

    const float* Ab = enc + (size_t)b * EE * NN + n0;
    const int lk  = tid >> 3;            // k row 0..31
    const int lnq = (tid & 7) * 16;      // col group (16 floats)

    const uint32_t as_base = (uint32_t)__cvta_generic_to_shared(AS);
    const uint32_t bh_base = (uint32_t)__cvta_generic_to_shared(BHs);
    const uint32_t bl_base = (uint32_t)__cvta_generic_to_shared(BLs);

#define L_ISSUE(KT, BUF)                                                         \
    do {                                                                         \
        const float* arow_ = Ab + (size_t)((KT) * KC + lk) * NN + lnq;           \
        const float* bhr_  = g_wwt_hi + (size_t)((KT) * KC + lk) * HH + lnq;     \
        const float* blr_  = g_wwt_lo + (size_t)((KT) * KC + lk) * HH + lnq;     \
        uint32_t off_ = ((BUF) * KC * APAD + lk * APAD + lnq) * 4;               \
        CP16(as_base + off_ + 0,  arow_ + 0);  CP16(as_base + off_ + 16, arow_ + 4); \
        CP16(as_base + off_ + 32, arow_ + 8);  CP16(as_base + off_ + 48, arow_ + 12);\
        CP16(bh_base + off_ + 0,  bhr_ + 0);   CP16(bh_base + off_ + 16, bhr_ + 4);  \
        CP16(bh_base + off_ + 32, bhr_ + 8);   CP16(bh_base + off_ + 48, bhr_ + 12); \
        CP16(bl_base + off_ + 0,  blr_ + 0);   CP16(bl_base + off_ + 16, blr_ + 4);  \
        CP16(bl_base + off_ + 32, blr_ + 8);   CP16(bl_base + off_ + 48, blr_ + 12); \
    } while (0)

    float c[16][4];
#pragma unroll
    for (int nt = 0; nt < 16; nt++)
#pragma unroll
        for (int q = 0; q < 4; q++) c[nt][q] = 0.f;

    L_ISSUE(0, 0);
    CP_COMMIT();
    int cur = 0;
    for (int kt = 0; kt < 8; kt++) {
        if (kt < 7) { L_ISSUE(kt + 1, cur ^ 1); CP_COMMIT(); CP_WAIT1(); }
        else        { CP_WAIT0(); }
        __syncthreads();

        const float* Ac = AS + cur * KC * APAD;
        const float* Bh = BHs + cur * KC * APAD;
        const float* Bl = BLs + cur * KC * APAD;
#pragma unroll
        for (int k8 = 0; k8 < 4; k8++) {
            const int kk = k8 * 8 + tig;
            const int m = m0 + gid;
            float x0 = Ac[kk * APAD + m];
            float x1 = Ac[kk * APAD + m + 8];
            float x2 = Ac[(kk + 4) * APAD + m];
            float x3 = Ac[(kk + 4) * APAD + m + 8];
            uint32_t ah[4], al[4];
            ah[0] = f2tf32(x0); al[0] = f2tf32(x0 - __uint_as_float(ah[0]));
            ah[1] = f2tf32(x1); al[1] = f2tf32(x1 - __uint_as_float(ah[1]));
            ah[2] = f2tf32(x2); al[2] = f2tf32(x2 - __uint_as_float(ah[2]));
            ah[3] = f2tf32(x3); al[3] = f2tf32(x3 - __uint_as_float(ah[3]));
#pragma unroll
            for (int nt = 0; nt < 16; nt++) {
                const int h = nt * 8 + gid;
                uint32_t bh0 = __float_as_uint(Bh[kk * APAD + h]);
                uint32_t bh1 = __float_as_uint(Bh[(kk + 4) * APAD + h]);
                uint32_t bl0 = __float_as_uint(Bl[kk * APAD + h]);
                uint32_t bl1 = __float_as_uint(Bl[(kk + 4) * APAD + h]);
                MMA_TF32(c[nt], ah, bh0, bh1);
                MMA_TF32(c[nt], al, bh0, bh1);
                MMA_TF32(c[nt], ah, bl0, bl1);
            }
        }
        __syncthreads();
        cur ^= 1;
    }
#undef L_ISSUE

    // epilogue: tanh + dot Vc; shfl over tig gives the complete h-sum per row
    float s0 = 0.f, s1 = 0.f;
#pragma unroll
    for (int nt = 0; nt < 16; nt++)
#pragma unroll
        for (int q = 0; q < 2; q++) {
            int h = nt * 8 + 2 * tig + q;
            s0 = fmaf(tanhf(c[nt][q]     + c2s[h]), vcs[h], s0);
            s1 = fmaf(tanhf(c[nt][2 + q] + c2s[h]), vcs[h], s1);
        }
    s0 += __shfl_xor_sync(0xffffffffu, s0, 1);
    s0 += __shfl_xor_sync(0xffffffffu, s0, 2);
    s1 += __shfl_xor_sync(0xffffffffu, s1, 1);
    s1 += __shfl_xor_sync(0xffffffffu, s1, 2);
    if (tig == 0) {
        out[(size_t)b * NN + n0 + m0 + gid]     = s0 + bvc0;
        out[(size_t)b * NN + n0 + m0 + gid + 8] = s1 + bvc0;
    }
}

// ---------------- k_final: log_softmax, mask, argmax, outputs ---------------
__global__ void k_final(const float* __restrict__ demand, const float* __restrict__ load,
                        const void* __restrict__ veh_cap_raw, float* __restrict__ out) {
    __shared__ float sred[NN];
    __shared__ float sval[NN];
    __shared__ int   sidx[NN];
    __shared__ float s_ndsel;
    __shared__ int   s_ptr;
    int b = blockIdx.x, n = threadIdx.x;

    float logit = out[(size_t)b * NN + n];
    sred[n] = logit;
    __syncthreads();
    for (int s = 256; s > 0; s >>= 1) {
        if (n < s) sred[n] = fmaxf(sred[n], sred[n + s]);
        __syncthreads();
    }
    float mx = sred[0];
    __syncthreads();
    sred[n] = expf(logit - mx);
    __syncthreads();
    for (int s = 256; s > 0; s >>= 1) {
        if (n < s) sred[n] += sred[n + s];
        __syncthreads();
    }
    float lse = mx + logf(sred[0]);

    float dm = demand[(size_t)b * NN + n];
    float ld = load[b];
    float lp = logit - lse;
    if (n > 0 && (dm == 0.f || ld == 0.f)) lp = __int_as_float(0xff800000); // -inf
    out[(size_t)b * NN + n] = lp;

    sval[n] = lp; sidx[n] = n;
    __syncthreads();
    for (int s = 256; s > 0; s >>= 1) {
        if (n < s) {
            float v2 = sval[n + s]; int i2 = sidx[n + s];
            if (v2 > sval[n] || (v2 == sval[n] && i2 < sidx[n])) { sval[n] = v2; sidx[n] = i2; }
        }
        __syncthreads();
    }
    if (n == 0) {
        int ptr = sidx[0];
        float dsel = demand[(size_t)b * NN + ptr];
        float capf = *(const float*)veh_cap_raw;
        int   capi = *(const int*)veh_cap_raw;
        float cap = (capf > 0.5f && capf < 1.0e6f) ? capf : (float)capi;
        bool depot = (ptr == 0);
        float nload = depot ? cap : (ld - dsel);
        float ndsel = depot ? dsel : (dsel - nload);
        out[(size_t)BB * NN + b]      = (float)ptr;
        out[(size_t)BB * NN + BB + b] = nload;
        s_ptr = ptr; s_ndsel = ndsel;
    }
    __syncthreads();
    float ndv = (n == s_ptr) ? s_ndsel : dm;
    out[(size_t)BB * NN + 2 * (size_t)BB + (size_t)b * NN + n] = ndv;
}

// ---------------- launch ----------------------------------------------------
extern "C" void kernel_launch(void* const* d_in, const int* in_sizes, int n_in,
                              void* d_out, int out_size) {
    const float* dec  = (const float*)d_in[0];
    const float* enc  = (const float*)d_in[1];
    const float* load = (const float*)d_in[2];
    const float* dem  = (const float*)d_in[3];
    const float* W1   = (const float*)d_in[4];
    const float* b1   = (const float*)d_in[5];
    const float* W2   = (const float*)d_in[6];
    const float* b2   = (const float*)d_in[7];
    const float* Wwt  = (const float*)d_in[8];
    const float* bwt  = (const float*)d_in[9];
    const float* Wct  = (const float*)d_in[10];
    const float* bct  = (const float*)d_in[11];
    const float* Wa   = (const float*)d_in[12];
    const float* ba   = (const float*)d_in[13];
    const float* Va   = (const float*)d_in[14];
    const float* bva  = (const float*)d_in[15];
    const float* Vc   = (const float*)d_in[16];
    const float* bvc  = (const float*)d_in[17];
    const void*  vcap = (const void*)d_in[18];
    float* out = (float*)d_out;

    const int SMEM_U = (2 * KC * APAD + 4 * KC * WPAD + 2 * AA) * 4;          // 55552
    const int SMEM_L = (6 * KC * APAD + 2 * HH) * 4;                           // 105472
    static int attr_done = 0;
    if (!attr_done) {
        cudaFuncSetAttribute(k_u_mma, cudaFuncAttributeMaxDynamicSharedMemorySize, SMEM_U);
        cudaFuncSetAttribute(k_logits_mma, cudaFuncAttributeMaxDynamicSharedMemorySize, SMEM_L);
        attr_done = 1;
    }

    k_pre<<<EE + BB, HH>>>(W1, Wa, Wwt, dec, W2, b1, b2, ba, bwt);
    k_u_mma<<<dim3(4, BB), 256, SMEM_U>>>(enc, Va, bva);
    k_soft<<<BB, 256>>>(enc, W1, Wct, bct);
    k_logits_mma<<<dim3(4, BB), 256, SMEM_L>>>(enc, Vc, bvc, out);
    k_final<<<BB, NN>>>(dem, load, vcap, out);
}